// round 4
// baseline (speedup 1.0000x reference)
#include <cuda_runtime.h>
#include <math.h>

#define FULL 0xffffffffu

constexpr int B     = 4;
constexpr int NS    = 16384;
constexpr int NG    = 2048;
constexpr int D     = 128;
constexpr int NC1   = 5;           // cells per dim (40 / 8)
constexpr int NCELL = NC1*NC1*NC1; // 125
constexpr int TOT_S = B*NS;        // 65536
constexpr int TOT_G = B*NG;        // 8192
constexpr float INV_SIG2 = 0.16f;  // 1/2.5^2
constexpr float R2CUT = 64.0f;     // 8^2

// ---------------- scratch (device globals: allocation-free) ----------------
__device__ int    d_s_cnt[B*NCELL];
__device__ int    d_g_cnt[B*NCELL];
__device__ int    d_s_start[B*NCELL+1];
__device__ int    d_g_start[B*NCELL+1];
__device__ int    d_s_items[TOT_S];     // original node idx (within batch), sorted by (batch,cell)
__device__ int    d_g_items[TOT_G];
__device__ float4 d_vs_s[TOT_S];        // coords in sorted order
__device__ float4 d_vg_s[TOT_G];
__device__ float4 d_xs_hs[TOT_S*32];    // relu(xs@Ws_pre+b), sorted rows, 128 f = 32 float4
__device__ float4 d_xg_hs[TOT_G*32];
__device__ float4 d_xs_ms[TOT_S*32];    // normalized surface messages (sorted rows)
__device__ float4 d_xg_ms[TOT_G*32];    // graph messages (sorted rows)
__device__ float  d_invr[TOT_S];        // 1/(rowsum + 1e-8), sorted surface order

__device__ __forceinline__ int cell_of(float x, float y, float z) {
    int cx = (int)(x * 0.125f); cx = cx < 0 ? 0 : (cx > 4 ? 4 : cx);
    int cy = (int)(y * 0.125f); cy = cy < 0 ? 0 : (cy > 4 ? 4 : cy);
    int cz = (int)(z * 0.125f); cz = cz < 0 ? 0 : (cz > 4 ? 4 : cz);
    return (cx * 5 + cy) * 5 + cz;
}

// ---------------- binning ----------------
__global__ void k_zero() {
    int t = blockIdx.x * blockDim.x + threadIdx.x;
    if (t < B*NCELL) { d_s_cnt[t] = 0; d_g_cnt[t] = 0; }
}

template<bool SURF>
__global__ void k_hist(const float* __restrict__ v) {
    constexpr int LOGN = SURF ? 14 : 11;
    int t = blockIdx.x * blockDim.x + threadIdx.x;   // exact grid, no bound check
    int b = t >> LOGN;
    float x = v[3*t], y = v[3*t+1], z = v[3*t+2];
    atomicAdd((SURF ? d_s_cnt : d_g_cnt) + b*NCELL + cell_of(x, y, z), 1);
}

// Parallel exclusive scan over the 500 cell counters (both arrays at once).
__global__ void k_scan() {
    __shared__ int sh_s[512];
    __shared__ int sh_g[512];
    int t = threadIdx.x;
    sh_s[t] = (t < B*NCELL) ? d_s_cnt[t] : 0;
    sh_g[t] = (t < B*NCELL) ? d_g_cnt[t] : 0;
    __syncthreads();
    #pragma unroll
    for (int off = 1; off < 512; off <<= 1) {
        int as = sh_s[t], ag = sh_g[t];
        int us = (t >= off) ? sh_s[t - off] : 0;
        int ug = (t >= off) ? sh_g[t - off] : 0;
        __syncthreads();
        sh_s[t] = as + us;
        sh_g[t] = ag + ug;
        __syncthreads();
    }
    if (t <= B*NCELL) {
        d_s_start[t] = (t == 0) ? 0 : sh_s[t - 1];
        d_g_start[t] = (t == 0) ? 0 : sh_g[t - 1];
    }
}

// Deterministic compaction: one warp per (batch,cell), scan nodes in index order.
template<bool SURF>
__global__ void k_build(const float* __restrict__ v) {
    constexpr int N = SURF ? NS : NG;
    int c = blockIdx.x;                 // cell
    int b = threadIdx.x >> 5;           // 4 warps = 4 batches
    int lane = threadIdx.x & 31;
    const int* startA = SURF ? d_s_start : d_g_start;
    int*       items  = SURF ? d_s_items : d_g_items;
    float4*    vsrt   = SURF ? d_vs_s   : d_vg_s;
    int pos = startA[b*NCELL + c];
    const float* vb = v + (size_t)b * N * 3;
    for (int base = 0; base < N; base += 32) {
        int n = base + lane;
        float x = vb[3*n], y = vb[3*n+1], z = vb[3*n+2];
        bool h = (cell_of(x, y, z) == c);
        unsigned m = __ballot_sync(FULL, h);
        if (h) {
            int p = pos + __popc(m & ((1u << lane) - 1u));
            items[p] = n;
            vsrt[p]  = make_float4(x, y, z, 0.f);
        }
        pos += __popc(m);
    }
}

// ---------------- fp32 GEMM: 128-row tiles, full N=128, BK=32 ----------------
constexpr int GM = 128;
constexpr int GT = 512;
constexpr int BK = 32;
constexpr int AS_STR = GM + 4;   // 132, pad to reduce bank conflicts

// Pre-encoder: Out[sorted i] = relu(X[orig row(i)] @ W + bias)
template<bool SURF>
__global__ __launch_bounds__(GT)
void k_gemm_pre(const float* __restrict__ X, const float* __restrict__ W,
                const float* __restrict__ bias) {
    constexpr int LOGN = SURF ? 14 : 11;
    const int* items = SURF ? d_s_items : d_g_items;
    float4*    Out   = SURF ? d_xs_hs  : d_xg_hs;

    __shared__ float As[BK * AS_STR];
    __shared__ float Wsh[BK * D];
    __shared__ int   rowoff[GM];

    int tid = threadIdx.x;
    int i0  = blockIdx.x * GM;
    if (tid < GM) {
        int i = i0 + tid; int b = i >> LOGN; int n = items[i];
        rowoff[tid] = ((b << LOGN) + n) * D;
    }
    __syncthreads();

    int c4 = tid & 31;
    int r0 = (tid >> 5) * 8;
    int lr = tid >> 2;
    int lf = tid & 3;

    float4 acc[8];
    #pragma unroll
    for (int rr = 0; rr < 8; rr++) acc[rr] = make_float4(0.f, 0.f, 0.f, 0.f);

    for (int k0 = 0; k0 < D; k0 += BK) {
        #pragma unroll
        for (int j = 0; j < 2; j++) {   // W chunk: 1024 float4 / 512 thr
            int id = tid + j * GT;
            int kk = id >> 5, cc = id & 31;
            reinterpret_cast<float4*>(Wsh)[id] =
                reinterpret_cast<const float4*>(W + (size_t)(k0 + kk) * D)[cc];
        }
        const float* xp = X + rowoff[lr] + k0;
        #pragma unroll
        for (int j = 0; j < 2; j++) {   // A chunk gathered, transposed into smem
            int f4 = lf + j * 4;
            float4 vv = reinterpret_cast<const float4*>(xp)[f4];
            int kk = f4 * 4;
            As[(kk+0)*AS_STR + lr] = vv.x;
            As[(kk+1)*AS_STR + lr] = vv.y;
            As[(kk+2)*AS_STR + lr] = vv.z;
            As[(kk+3)*AS_STR + lr] = vv.w;
        }
        __syncthreads();
        #pragma unroll
        for (int kk = 0; kk < BK; kk++) {
            float4 w4 = *reinterpret_cast<const float4*>(&Wsh[kk*D + c4*4]);
            float4 A0 = *reinterpret_cast<const float4*>(&As[kk*AS_STR + r0]);
            float4 A1 = *reinterpret_cast<const float4*>(&As[kk*AS_STR + r0 + 4]);
            float a[8] = {A0.x, A0.y, A0.z, A0.w, A1.x, A1.y, A1.z, A1.w};
            #pragma unroll
            for (int rr = 0; rr < 8; rr++) {
                acc[rr].x += a[rr] * w4.x;
                acc[rr].y += a[rr] * w4.y;
                acc[rr].z += a[rr] * w4.z;
                acc[rr].w += a[rr] * w4.w;
            }
        }
        __syncthreads();
    }
    float4 bb = reinterpret_cast<const float4*>(bias)[c4];
    #pragma unroll
    for (int rr = 0; rr < 8; rr++) {
        float4 o;
        o.x = fmaxf(acc[rr].x + bb.x, 0.f);
        o.y = fmaxf(acc[rr].y + bb.y, 0.f);
        o.z = fmaxf(acc[rr].z + bb.z, 0.f);
        o.w = fmaxf(acc[rr].w + bb.w, 0.f);
        Out[(size_t)(i0 + r0 + rr) * 32 + c4] = o;
    }
}

// Post block: out[orig row] = relu([H | Msg] @ W + bias), scatter to d_out
template<bool SURF>
__global__ __launch_bounds__(GT)
void k_gemm_post(const float* __restrict__ W, const float* __restrict__ bias,
                 float* __restrict__ out) {
    constexpr int LOGN = SURF ? 14 : 11;
    constexpr int OB   = SURF ? 0 : NS;
    const float4* H   = SURF ? d_xs_hs : d_xg_hs;
    const float4* Msg = SURF ? d_xs_ms : d_xg_ms;
    const int* items  = SURF ? d_s_items : d_g_items;

    __shared__ float As[BK * AS_STR];
    __shared__ float Wsh[BK * D];
    __shared__ int   orow[GM];

    int tid = threadIdx.x;
    int i0  = blockIdx.x * GM;
    if (tid < GM) {
        int i = i0 + tid; int b = i >> LOGN; int n = items[i];
        orow[tid] = b * (NS + NG) + OB + n;
    }
    __syncthreads();

    int c4 = tid & 31;
    int r0 = (tid >> 5) * 8;
    int lr = tid >> 2;
    int lf = tid & 3;

    float4 acc[8];
    #pragma unroll
    for (int rr = 0; rr < 8; rr++) acc[rr] = make_float4(0.f, 0.f, 0.f, 0.f);

    for (int k0 = 0; k0 < 2*D; k0 += BK) {
        #pragma unroll
        for (int j = 0; j < 2; j++) {
            int id = tid + j * GT;
            int kk = id >> 5, cc = id & 31;
            reinterpret_cast<float4*>(Wsh)[id] =
                reinterpret_cast<const float4*>(W + (size_t)(k0 + kk) * D)[cc];
        }
        const float4* src = (k0 < D) ? H : Msg;
        int koff4 = (k0 & (D - 1)) >> 2;
        const float4* xp = src + (size_t)(i0 + lr) * 32 + koff4;
        #pragma unroll
        for (int j = 0; j < 2; j++) {
            int f4 = lf + j * 4;
            float4 vv = xp[f4];
            int kk = f4 * 4;
            As[(kk+0)*AS_STR + lr] = vv.x;
            As[(kk+1)*AS_STR + lr] = vv.y;
            As[(kk+2)*AS_STR + lr] = vv.z;
            As[(kk+3)*AS_STR + lr] = vv.w;
        }
        __syncthreads();
        #pragma unroll
        for (int kk = 0; kk < BK; kk++) {
            float4 w4 = *reinterpret_cast<const float4*>(&Wsh[kk*D + c4*4]);
            float4 A0 = *reinterpret_cast<const float4*>(&As[kk*AS_STR + r0]);
            float4 A1 = *reinterpret_cast<const float4*>(&As[kk*AS_STR + r0 + 4]);
            float a[8] = {A0.x, A0.y, A0.z, A0.w, A1.x, A1.y, A1.z, A1.w};
            #pragma unroll
            for (int rr = 0; rr < 8; rr++) {
                acc[rr].x += a[rr] * w4.x;
                acc[rr].y += a[rr] * w4.y;
                acc[rr].z += a[rr] * w4.z;
                acc[rr].w += a[rr] * w4.w;
            }
        }
        __syncthreads();
    }
    float4 bb = reinterpret_cast<const float4*>(bias)[c4];
    #pragma unroll
    for (int rr = 0; rr < 8; rr++) {
        float4 o;
        o.x = fmaxf(acc[rr].x + bb.x, 0.f);
        o.y = fmaxf(acc[rr].y + bb.y, 0.f);
        o.z = fmaxf(acc[rr].z + bb.z, 0.f);
        o.w = fmaxf(acc[rr].w + bb.w, 0.f);
        float* op = out + (size_t)orow[r0 + rr] * D + c4 * 4;
        *reinterpret_cast<float4*>(op) = o;
    }
}

// ---------------- message passing: surface gather (graph -> surface) ----------------
// one warp per sorted surface node; lane owns dims [4*lane, 4*lane+4)
// Z-strip merge: for each of <=9 (X,Y) columns, the Z-neighbor cells are
// contiguous in cell-id AND (counting sort) contiguous in the node array.
__global__ __launch_bounds__(512)
void k_mps() {
    int w    = blockIdx.x * 16 + (threadIdx.x >> 5);   // sorted surface index
    int lane = threadIdx.x & 31;
    int b    = w >> 14;
    float4 p = d_vs_s[w];
    int cx = (int)(p.x * 0.125f); cx = cx < 0 ? 0 : (cx > 4 ? 4 : cx);
    int cy = (int)(p.y * 0.125f); cy = cy < 0 ? 0 : (cy > 4 ? 4 : cy);
    int cz = (int)(p.z * 0.125f); cz = cz < 0 ? 0 : (cz > 4 ? 4 : cz);
    int z0 = cz > 0 ? cz - 1 : 0;
    int z1 = cz < 4 ? cz + 1 : 4;

    float4 acc = make_float4(0.f, 0.f, 0.f, 0.f);
    float rs = 0.f;

    for (int dx = -1; dx <= 1; dx++) {
        int X = cx + dx; if ((unsigned)X > 4u) continue;
        for (int dy = -1; dy <= 1; dy++) {
            int Y = cy + dy; if ((unsigned)Y > 4u) continue;
            int cb = b * NCELL + (X * 5 + Y) * 5;
            int s0 = d_g_start[cb + z0], s1 = d_g_start[cb + z1 + 1];
            for (int base = s0; base < s1; base += 32) {
                int j = base + lane;
                float wv = 0.f;
                if (j < s1) {
                    float4 q = d_vg_s[j];
                    float ddx = p.x - q.x;
                    float ddy = p.y - q.y;
                    float ddz = p.z - q.z;
                    float d2 = ddx*ddx + ddy*ddy + ddz*ddz;
                    if (d2 < R2CUT) wv = __expf(-INV_SIG2 * d2);
                }
                rs += wv;
                unsigned m = __ballot_sync(FULL, wv > 0.f);
                while (m) {
                    int t = __ffs(m) - 1; m &= m - 1;
                    float ww = __shfl_sync(FULL, wv, t);
                    float4 g = d_xg_hs[(size_t)(base + t) * 32 + lane];
                    acc.x += ww * g.x; acc.y += ww * g.y;
                    acc.z += ww * g.z; acc.w += ww * g.w;
                }
            }
        }
    }
    #pragma unroll
    for (int o = 16; o; o >>= 1) rs += __shfl_xor_sync(FULL, rs, o);
    float inv = 1.f / (rs + 1e-8f);
    acc.x *= inv; acc.y *= inv; acc.z *= inv; acc.w *= inv;
    d_xs_ms[(size_t)w * 32 + lane] = acc;
    if (lane == 0) d_invr[w] = inv;
}

// ---------------- message passing: graph gather (surface -> graph) ----------------
// one warp per sorted graph node; same Z-strip merge over surface spans.
// Uses d_invr (surface rowsum) since w is row-normalized along the surface dim.
__global__ __launch_bounds__(512)
void k_mpg() {
    int w    = blockIdx.x * 16 + (threadIdx.x >> 5);  // sorted graph index
    int lane = threadIdx.x & 31;
    int b    = w >> 11;
    float4 p = d_vg_s[w];
    int cx = (int)(p.x * 0.125f); cx = cx < 0 ? 0 : (cx > 4 ? 4 : cx);
    int cy = (int)(p.y * 0.125f); cy = cy < 0 ? 0 : (cy > 4 ? 4 : cy);
    int cz = (int)(p.z * 0.125f); cz = cz < 0 ? 0 : (cz > 4 ? 4 : cz);
    int z0 = cz > 0 ? cz - 1 : 0;
    int z1 = cz < 4 ? cz + 1 : 4;

    float4 acc = make_float4(0.f, 0.f, 0.f, 0.f);

    for (int dx = -1; dx <= 1; dx++) {
        int X = cx + dx; if ((unsigned)X > 4u) continue;
        for (int dy = -1; dy <= 1; dy++) {
            int Y = cy + dy; if ((unsigned)Y > 4u) continue;
            int cb = b * NCELL + (X * 5 + Y) * 5;
            int s0 = d_s_start[cb + z0], s1 = d_s_start[cb + z1 + 1];
            for (int base = s0; base < s1; base += 32) {
                int j = base + lane;
                float wv = 0.f;
                if (j < s1) {
                    float4 q = d_vs_s[j];
                    float ddx = p.x - q.x;
                    float ddy = p.y - q.y;
                    float ddz = p.z - q.z;
                    float d2 = ddx*ddx + ddy*ddy + ddz*ddz;
                    if (d2 < R2CUT) wv = __expf(-INV_SIG2 * d2) * d_invr[j];
                }
                unsigned m = __ballot_sync(FULL, wv > 0.f);
                while (m) {
                    int t = __ffs(m) - 1; m &= m - 1;
                    float ww = __shfl_sync(FULL, wv, t);
                    float4 g = d_xs_hs[(size_t)(base + t) * 32 + lane];
                    acc.x += ww * g.x; acc.y += ww * g.y;
                    acc.z += ww * g.z; acc.w += ww * g.w;
                }
            }
        }
    }
    d_xg_ms[(size_t)w * 32 + lane] = acc;
}

// ---------------- launch ----------------
extern "C" void kernel_launch(void* const* d_in, const int* in_sizes, int n_in,
                              void* d_out, int out_size) {
    const float* xs      = (const float*)d_in[0];
    const float* xg      = (const float*)d_in[1];
    const float* vs      = (const float*)d_in[2];
    const float* vg      = (const float*)d_in[3];
    const float* Ws_pre  = (const float*)d_in[4];
    const float* bs_pre  = (const float*)d_in[5];
    const float* Wg_pre  = (const float*)d_in[6];
    const float* bg_pre  = (const float*)d_in[7];
    const float* Ws_post = (const float*)d_in[8];
    const float* bs_post = (const float*)d_in[9];
    const float* Wg_post = (const float*)d_in[10];
    const float* bg_post = (const float*)d_in[11];
    float* out = (float*)d_out;
    (void)in_sizes; (void)n_in; (void)out_size;

    k_zero<<<1, 512>>>();
    k_hist<true><<<TOT_S / 256, 256>>>(vs);
    k_hist<false><<<TOT_G / 256, 256>>>(vg);
    k_scan<<<1, 512>>>();
    k_build<true><<<NCELL, 128>>>(vs);
    k_build<false><<<NCELL, 128>>>(vg);

    k_gemm_pre<true><<<TOT_S / GM, GT>>>(xs, Ws_pre, bs_pre);
    k_gemm_pre<false><<<TOT_G / GM, GT>>>(xg, Wg_pre, bg_pre);

    k_mps<<<TOT_S / 16, 512>>>();
    k_mpg<<<TOT_G / 16, 512>>>();

    k_gemm_post<true><<<TOT_S / GM, GT>>>(Ws_post, bs_post, out);
    k_gemm_post<false><<<TOT_G / GM, GT>>>(Wg_post, bg_post, out);
}